// round 4
// baseline (speedup 1.0000x reference)
#include <cuda_runtime.h>

// Problem constants
#define BQ     16
#define DIMD   128
#define TT     4096
#define NC     1024
#define NTOT   (BQ * TT)           // 65536 rows
#define QELEMS (BQ * DIMD * TT)    // 8388608 output quantized elems
#define NBLK   (NTOT / 128)        // 512 blocks (128 t-rows each)
#define FLAGCAP 4096

// Device scratch (no allocations allowed in kernel_launch)
__device__ float    g_halfnorm[NC];
__device__ float    g_ee[NC];          // strict sequential ||e||^2 (ref replication)
__device__ int      g_indices[NTOT];
__device__ float    g_partial[NBLK];
__device__ unsigned g_used[NC];
__device__ int      g_flagcount;
__device__ int      g_flagged[FLAGCAP];

// ---- packed fp32x2 helpers (Blackwell FFMA2 path; exact fp32 .rn semantics) ----
__device__ __forceinline__ void fma2(unsigned long long& acc,
                                     unsigned long long a,
                                     unsigned long long b) {
    asm("fma.rn.f32x2 %0, %1, %2, %0;" : "+l"(acc) : "l"(a), "l"(b));
}
__device__ __forceinline__ unsigned long long pack2(float v) {
    unsigned long long r;
    unsigned int u = __float_as_uint(v);
    asm("mov.b64 %0, {%1, %1};" : "=l"(r) : "r"(u));
    return r;
}
__device__ __forceinline__ void unpack2(unsigned long long p, float& lo, float& hi) {
    unsigned int a, b;
    asm("mov.b64 {%0, %1}, %2;" : "=r"(a), "=r"(b) : "l"(p));
    lo = __uint_as_float(a);
    hi = __uint_as_float(b);
}

// ---------------------------------------------------------------------------
// Kernel 0: halfnorm + strict-sequential ee ; zero used[] and flag count
// ---------------------------------------------------------------------------
__global__ void prep_kernel(const float* __restrict__ embed) {
    int j = blockIdx.x * blockDim.x + threadIdx.x;
    if (j == 0) g_flagcount = 0;
    if (j < NC) {
        const float* row = embed + (size_t)j * DIMD;
        // strict scalar-sequential fp32, mul-then-add (no FMA): ref replication
        float s = 0.f;
        for (int k = 0; k < DIMD; k++)
            s = __fadd_rn(s, __fmul_rn(row[k], row[k]));
        g_ee[j] = s;
        g_halfnorm[j] = 0.5f * s;
        g_used[j] = 0u;
    }
}

// ---------------------------------------------------------------------------
// Kernel 1: per-row argmax_j ( x . e_j - halfnorm_j ) with exact fp32x2 math.
// Tracks top-2 scores; rows whose d2 top-2 gap < 4*ulp(||x||^2-scale) are
// flagged for exact reference-arithmetic replication (repair_kernel).
// Block = 128 t-rows (one b), 256 threads, 8x8 register tile per thread,
// codes in 8 chunks of 128. halfnorm folded as K-row 128 with x = -1.
// ---------------------------------------------------------------------------
__global__ __launch_bounds__(256, 1)
void argmin_kernel(const float* __restrict__ x, const float* __restrict__ embed) {
    extern __shared__ float sm[];
    float* xs   = sm;                         // [129][128]  xs[k*128+m] = x[b,k,t0+m]
    float* es   = sm + 129 * 128;             // [129][stride 129]
    float* stau = sm + 129 * 128 + 129 * 129; // [128] per-row flag threshold (score units)

    const int tid = threadIdx.x;
    const int tx  = tid & 15;         // code direction (16 threads)
    const int ty  = tid >> 4;         // row direction  (16 groups of 8 rows)
    const int b   = blockIdx.x >> 5;  // 32 tiles of t per batch
    const int t0  = (blockIdx.x & 31) * 128;

    // Load x tile (coalesced in t), plus the -1 row for the halfnorm trick
    const float* xb = x + (size_t)b * DIMD * TT + t0;
    for (int l = tid; l < 128 * 128; l += 256) {
        int k = l >> 7, m = l & 127;
        xs[l] = xb[(size_t)k * TT + m];
    }
    if (tid < 128) xs[128 * 128 + tid] = -1.0f;
    __syncthreads();

    // Per-row ||x||^2 -> flag threshold. d2 grid G = 2^(E-23) (E = exponent
    // of xx); flag when d2 top-2 gap < 4G, i.e. score gap < 2G = 2^(E-22).
    if (tid < 128) {
        float s = 0.f;
        for (int k = 0; k < 128; k++) {
            float v = xs[k * 128 + tid];
            s += v * v;
        }
        int E = (int)((__float_as_uint(s) >> 23) & 0xFF) - 127;
        stau[tid] = __uint_as_float((unsigned)(E - 22 + 127) << 23);
    }
    __syncthreads();

    // Per-thread top-2 over this thread's codes, for 8 rows each
    float b1[8], b2[8];
    int   bi[8];
#pragma unroll
    for (int i = 0; i < 8; i++) { b1[i] = -3.4e38f; b2[i] = -3.4e38f; bi[i] = 0; }

    for (int chunk = 0; chunk < 8; chunk++) {
        const int code0 = chunk * 128;
        __syncthreads();  // protect es from previous chunk's readers
        for (int l = tid; l < 128 * 128; l += 256) {
            int j = l >> 7, k = l & 127;
            es[k * 129 + j] = embed[(size_t)(code0 + j) * DIMD + k];
        }
        if (tid < 128) es[128 * 129 + tid] = g_halfnorm[code0 + tid];
        __syncthreads();

        unsigned long long acc[8][4];
#pragma unroll
        for (int j = 0; j < 8; j++)
#pragma unroll
            for (int p = 0; p < 4; p++) acc[j][p] = 0ull;

        const float* xrow = xs + ty * 8;
        const float* erow = es + tx * 8;
        for (int k = 0; k <= 128; k++) {
            ulonglong2 xa = *(const ulonglong2*)(xrow + k * 128);      // rows 0..3
            ulonglong2 xc = *(const ulonglong2*)(xrow + k * 128 + 4);  // rows 4..7
#pragma unroll
            for (int j = 0; j < 8; j++) {
                unsigned long long e2 = pack2(erow[k * 129 + j]);
                fma2(acc[j][0], xa.x, e2);
                fma2(acc[j][1], xa.y, e2);
                fma2(acc[j][2], xc.x, e2);
                fma2(acc[j][3], xc.y, e2);
            }
        }

        // top-2 update, ascending code index (first-max kept)
#pragma unroll
        for (int j = 0; j < 8; j++) {
            int jg = code0 + tx * 8 + j;
#pragma unroll
            for (int p = 0; p < 4; p++) {
                float s0, s1;
                unpack2(acc[j][p], s0, s1);
                int r0 = 2 * p, r1 = 2 * p + 1;
                if (s0 > b1[r0]) { b2[r0] = b1[r0]; b1[r0] = s0; bi[r0] = jg; }
                else if (s0 > b2[r0]) b2[r0] = s0;
                if (s1 > b1[r1]) { b2[r1] = b1[r1]; b1[r1] = s1; bi[r1] = jg; }
                else if (s1 > b2[r1]) b2[r1] = s1;
            }
        }
    }

    // cross-thread reduction: merge 16 tx (b1,b2,idx) triples per row
    __syncthreads();
    float* rb1 = sm;                           // [128][16]
    float* rb2 = sm + 128 * 16;                // [128][16]
    int*   rji = (int*)(sm + 2 * 128 * 16);    // [128][16]
#pragma unroll
    for (int i = 0; i < 8; i++) {
        int row = ty * 8 + i;
        rb1[row * 16 + tx] = b1[i];
        rb2[row * 16 + tx] = b2[i];
        rji[row * 16 + tx] = bi[i];
    }
    __syncthreads();
    if (tid < 128) {
        float v1 = rb1[tid * 16];
        float v2 = rb2[tid * 16];
        int   vi = rji[tid * 16];
#pragma unroll
        for (int c = 1; c < 16; c++) {
            float o1 = rb1[tid * 16 + c];
            float o2 = rb2[tid * 16 + c];
            int   oi = rji[tid * 16 + c];
            if (o1 > v1) {
                v2 = fmaxf(v1, o2);
                v1 = o1; vi = oi;
            } else {
                v2 = fmaxf(v2, o1);          // handles o1 == v1 (tie -> gap 0)
                if (o1 == v1 && oi < vi) vi = oi;
            }
        }
        int n = b * TT + t0 + tid;
        g_indices[n] = vi;
        if (v1 - v2 < stau[tid]) {           // near-tie: defer to exact replication
            int slot = atomicAdd(&g_flagcount, 1);
            if (slot < FLAGCAP) g_flagged[slot] = n;
        }
    }
}

// ---------------------------------------------------------------------------
// Kernel 1.5: exact reference-arithmetic replication for flagged rows.
// d2_j = fl( fl( xx - fl(2*xe_j) ) + ee_j ), all strict fp32 mul/add,
// xx strict scalar-sequential; argmin with first-occurrence tie-break.
// ---------------------------------------------------------------------------
__global__ __launch_bounds__(256, 1)
void repair_kernel(const float* __restrict__ x, const float* __restrict__ embed) {
    __shared__ float xv[128];
    __shared__ float xxs;
    __shared__ float rv[256];
    __shared__ int   rix[256];
    const int tid = threadIdx.x;
    int nflag = *(volatile int*)&g_flagcount;
    if (nflag > FLAGCAP) nflag = FLAGCAP;

    for (int f = blockIdx.x; f < nflag; f += gridDim.x) {
        int n = g_flagged[f];
        int b = n >> 12, t = n & 4095;
        if (tid < 128) xv[tid] = x[(size_t)b * DIMD * TT + (size_t)tid * TT + t];
        __syncthreads();
        if (tid == 0) {
            float s = 0.f;
            for (int k = 0; k < 128; k++)
                s = __fadd_rn(s, __fmul_rn(xv[k], xv[k]));
            xxs = s;
        }
        __syncthreads();
        float xx = xxs;

        float bd = 3.4e38f;
        int   bj = 0;
        // each thread: 4 consecutive codes, ascending
#pragma unroll 1
        for (int q = 0; q < 4; q++) {
            int j = tid * 4 + q;
            const float* e = embed + (size_t)j * DIMD;
            float xe = 0.f;
            for (int k = 0; k < 128; k++)
                xe = __fadd_rn(xe, __fmul_rn(xv[k], e[k]));
            float s1 = __fadd_rn(xx, __fmul_rn(-2.0f, xe));  // fl(xx - 2*xe)
            float d2 = __fadd_rn(s1, g_ee[j]);               // fl(.. + ee)
            if (d2 < bd) { bd = d2; bj = j; }
        }
        rv[tid] = bd; rix[tid] = bj;
        __syncthreads();
        for (int s = 128; s > 0; s >>= 1) {
            if (tid < s) {
                float ov = rv[tid + s]; int oj = rix[tid + s];
                if (ov < rv[tid] || (ov == rv[tid] && oj < rix[tid])) {
                    rv[tid] = ov; rix[tid] = oj;
                }
            }
            __syncthreads();
        }
        if (tid == 0) g_indices[n] = rix[0];
        __syncthreads();
    }
}

// ---------------------------------------------------------------------------
// Kernel 2: gather quantized rows -> [B,D,T] output (coalesced in t),
// fused: indices (as float), used-marking, diff^2 partial sums.
// ---------------------------------------------------------------------------
__global__ __launch_bounds__(256, 1)
void gather_kernel(const float* __restrict__ x, const float* __restrict__ embed,
                   float* __restrict__ out) {
    extern __shared__ float sm2[];
    float* qs   = sm2;                       // [128 rows][stride 129]
    int*   sidx = (int*)(sm2 + 128 * 129);   // [128]
    float* red  = (float*)(sidx + 128);      // [256]

    const int tid = threadIdx.x;
    const int b   = blockIdx.x >> 5;
    const int t0  = (blockIdx.x & 31) * 128;

    if (tid < 128) {
        int n = b * TT + t0 + tid;
        int v = g_indices[n];
        sidx[tid] = v;
        g_used[v] = 1u;                      // benign race, deterministic result
        out[QELEMS + n] = (float)v;          // indices as float
    }
    __syncthreads();

    // stage the 128 selected codebook rows into smem (pad 129: conflict-free)
    {
        int m = tid >> 1, half = tid & 1;
        const float4* er = (const float4*)(embed + (size_t)sidx[m] * DIMD) + half * 16;
        float* qrow = qs + m * 129 + half * 64;
#pragma unroll
        for (int q = 0; q < 16; q++) {
            float4 v = er[q];
            qrow[q * 4 + 0] = v.x; qrow[q * 4 + 1] = v.y;
            qrow[q * 4 + 2] = v.z; qrow[q * 4 + 3] = v.w;
        }
    }
    __syncthreads();

    const int m  = tid & 127;
    const int dd = tid >> 7;
    const float* xb = x   + (size_t)b * DIMD * TT + t0 + m;
    float*       ob = out + (size_t)b * DIMD * TT + t0 + m;
    float lacc = 0.f;
    for (int d0 = 0; d0 < 128; d0 += 2) {
        int d = d0 + dd;
        float q  = qs[m * 129 + d];
        float xv = xb[(size_t)d * TT];
        ob[(size_t)d * TT] = q;              // coalesced in m
        float diff = xv - q;
        lacc += diff * diff;
    }
    red[tid] = lacc;
    __syncthreads();
    for (int s = 128; s > 0; s >>= 1) {
        if (tid < s) red[tid] += red[tid + s];
        __syncthreads();
    }
    if (tid == 0) g_partial[blockIdx.x] = red[0];
}

// ---------------------------------------------------------------------------
// Kernel 3: deterministic final reduction -> loss, utilization
// ---------------------------------------------------------------------------
__global__ void finalize_kernel(float* __restrict__ out) {
    __shared__ float rs[512];
    __shared__ float us[512];
    int tid = threadIdx.x;
    rs[tid] = g_partial[tid];
    us[tid] = (float)(g_used[tid] + g_used[tid + 512]);
    __syncthreads();
    for (int s = 256; s > 0; s >>= 1) {
        if (tid < s) { rs[tid] += rs[tid + s]; us[tid] += us[tid + s]; }
        __syncthreads();
    }
    if (tid == 0) {
        out[QELEMS + NTOT]     = 2.0f * rs[0] / (float)QELEMS;  // 2*mean(diff^2)
        out[QELEMS + NTOT + 1] = us[0] / (float)NC;
    }
}

// ---------------------------------------------------------------------------
extern "C" void kernel_launch(void* const* d_in, const int* in_sizes, int n_in,
                              void* d_out, int out_size) {
    (void)in_sizes; (void)n_in; (void)out_size;
    const float* x     = (const float*)d_in[0];
    const float* embed = (const float*)d_in[1];
    float*       out   = (float*)d_out;

    const int smem1 = (129 * 128 + 129 * 129 + 128) * 4;      // 133,124 B
    const int smem2 = 128 * 129 * 4 + 128 * 4 + 256 * 4;      //  67,584 B
    cudaFuncSetAttribute(argmin_kernel, cudaFuncAttributeMaxDynamicSharedMemorySize, smem1);
    cudaFuncSetAttribute(gather_kernel, cudaFuncAttributeMaxDynamicSharedMemorySize, smem2);

    prep_kernel<<<4, 256>>>(embed);
    argmin_kernel<<<NBLK, 256, smem1>>>(x, embed);
    repair_kernel<<<16, 256>>>(x, embed);
    gather_kernel<<<NBLK, 256, smem2>>>(x, embed, out);
    finalize_kernel<<<1, 512>>>(out);
}

// round 7
// speedup vs baseline: 2.4885x; 2.4885x over previous
#include <cuda_runtime.h>
#include <cuda_bf16.h>
#include <cstdint>
#include <cfloat>

// Problem constants
#define BQ     16
#define DIMD   128
#define TT     4096
#define NC     1024
#define NTOT   (BQ * TT)           // 65536 rows
#define QELEMS (BQ * DIMD * TT)    // 8388608 output quantized elems
#define NBLK   256                 // 256 blocks x 256 rows
#define FLAGCAP 4096

// Device scratch (no allocations allowed in kernel_launch)
__device__ float    g_halfnorm[NC];
__device__ float    g_ee[NC];          // strict sequential ||e||^2 (ref replication)
__device__ float    g_partial[NBLK];
__device__ unsigned g_used[NC];
__device__ int      g_flagcount;
__device__ int      g_flagged[FLAGCAP];
__device__ __align__(16) __nv_bfloat16 g_ehi[NC * DIMD];
__device__ __align__(16) __nv_bfloat16 g_elo[NC * DIMD];

// ---------------- helpers ----------------
__device__ __forceinline__ uint32_t smem_u32(const void* p) {
    uint32_t a;
    asm("{ .reg .u64 t; cvta.to.shared.u64 t, %1; cvt.u32.u64 %0, t; }"
        : "=r"(a) : "l"(p));
    return a;
}
__device__ __forceinline__ uint4 ldm_x4(uint32_t addr) {
    uint4 r;
    asm volatile("ldmatrix.sync.aligned.m8n8.x4.shared.b16 {%0,%1,%2,%3}, [%4];"
                 : "=r"(r.x), "=r"(r.y), "=r"(r.z), "=r"(r.w) : "r"(addr));
    return r;
}
__device__ __forceinline__ void mma16816(float4& c, const uint4& a,
                                         uint32_t b0, uint32_t b1) {
    asm volatile(
        "mma.sync.aligned.m16n8k16.row.col.f32.bf16.bf16.f32 "
        "{%0,%1,%2,%3}, {%4,%5,%6,%7}, {%8,%9}, {%0,%1,%2,%3};"
        : "+f"(c.x), "+f"(c.y), "+f"(c.z), "+f"(c.w)
        : "r"(a.x), "r"(a.y), "r"(a.z), "r"(a.w), "r"(b0), "r"(b1));
}

// SMEM layout (bytes). Row stride 136 bf16 elements (272 B) -> conflict-free
// ldmatrix (bank group 4*row mod 32, disjoint 16B windows).
#define KPAD   136
#define OFF_XHI  0
#define OFF_XLO  69632              // 256*136*2
#define OFF_EHI  139264
#define OFF_ELO  174080             // + 128*136*2
#define OFF_HN   208896
#define OFF_XX   212992
#define OFF_SIDX 214016
#define OFF_RV1  215040
#define OFF_RV2  216064
#define OFF_RVI  217088
#define OFF_RED  218112
#define SMEM_MAIN 219136
#define OFF_QS   0                  // gather staging alias [256][129] f32

// ---------------------------------------------------------------------------
// Kernel 0: halfnorm + strict-sequential ee + bf16 hi/lo split of embed
// ---------------------------------------------------------------------------
__global__ void prep_kernel(const float* __restrict__ embed) {
    int j = blockIdx.x * blockDim.x + threadIdx.x;
    if (j == 0) g_flagcount = 0;
    if (j < NC) {
        const float* row = embed + (size_t)j * DIMD;
        float s = 0.f;
        for (int k = 0; k < DIMD; k++) {
            float v = row[k];
            s = __fadd_rn(s, __fmul_rn(v, v));     // strict seq: ref replication
            __nv_bfloat16 hi = __float2bfloat16_rn(v);
            __nv_bfloat16 lo = __float2bfloat16_rn(v - __bfloat162float(hi));
            g_ehi[j * DIMD + k] = hi;
            g_elo[j * DIMD + k] = lo;
        }
        g_ee[j] = s;
        g_halfnorm[j] = 0.5f * s;
        g_used[j] = 0u;
    }
}

// ---------------------------------------------------------------------------
// Kernel 1: mma.sync bf16 3-split GEMM + argmax + fused gather/loss/output.
// Block = 256 t-rows of one batch, 256 threads, 8 warps x 32 rows.
// ---------------------------------------------------------------------------
__global__ __launch_bounds__(256, 1)
void vq_main_kernel(const float* __restrict__ x, const float* __restrict__ embed,
                    float* __restrict__ out) {
    extern __shared__ char smem[];
    const uint32_t smb = smem_u32(smem);
    float* hn    = (float*)(smem + OFF_HN);
    float* xx_sm = (float*)(smem + OFF_XX);
    int*   sidx  = (int*)(smem + OFF_SIDX);
    float* rv1   = (float*)(smem + OFF_RV1);
    float* rv2   = (float*)(smem + OFF_RV2);
    int*   rvi   = (int*)(smem + OFF_RVI);
    float* red   = (float*)(smem + OFF_RED);

    const int tid  = threadIdx.x;
    const int lane = tid & 31;
    const int w    = tid >> 5;
    const int b_   = blockIdx.x >> 4;
    const int t0   = (blockIdx.x & 15) * 256;

    // ---- 1. load x column-slab, split bf16 hi/lo, per-row ||x||^2 ----
    {
        const float* xb = x + (size_t)b_ * DIMD * TT + t0 + tid;   // row m = tid
        float xx = 0.f;
        char* hrow = smem + OFF_XHI + tid * (KPAD * 2);
        char* lrow = smem + OFF_XLO + tid * (KPAD * 2);
#pragma unroll 4
        for (int k0 = 0; k0 < 128; k0 += 4) {
            float v0 = xb[(size_t)(k0 + 0) * TT];
            float v1_ = xb[(size_t)(k0 + 1) * TT];
            float v2_ = xb[(size_t)(k0 + 2) * TT];
            float v3 = xb[(size_t)(k0 + 3) * TT];
            xx += v0 * v0 + v1_ * v1_ + v2_ * v2_ + v3 * v3;
            __nv_bfloat16 h0 = __float2bfloat16_rn(v0);
            __nv_bfloat16 h1 = __float2bfloat16_rn(v1_);
            __nv_bfloat16 h2 = __float2bfloat16_rn(v2_);
            __nv_bfloat16 h3 = __float2bfloat16_rn(v3);
            __nv_bfloat162 hp0 = {h0, h1}, hp1 = {h2, h3};
            __nv_bfloat162 lp0 = {__float2bfloat16_rn(v0 - __bfloat162float(h0)),
                                  __float2bfloat16_rn(v1_ - __bfloat162float(h1))};
            __nv_bfloat162 lp1 = {__float2bfloat16_rn(v2_ - __bfloat162float(h2)),
                                  __float2bfloat16_rn(v3 - __bfloat162float(h3))};
            *(uint2*)(hrow + k0 * 2) =
                make_uint2(*(uint32_t*)&hp0, *(uint32_t*)&hp1);
            *(uint2*)(lrow + k0 * 2) =
                make_uint2(*(uint32_t*)&lp0, *(uint32_t*)&lp1);
        }
        xx_sm[tid] = xx;
    }
    for (int l = tid; l < NC; l += 256) hn[l] = g_halfnorm[l];
    __syncthreads();

    // ---- 2. preload A fragments (2 tiles x 8 ksteps x hi/lo) ----
    uint4 ahi[2][8], alo[2][8];
#pragma unroll
    for (int t = 0; t < 2; t++) {
#pragma unroll
        for (int ks = 0; ks < 8; ks++) {
            int rA = w * 32 + t * 16 + (lane & 7) + ((lane >> 3) & 1) * 8;
            int cA = ks * 16 + (lane >> 4) * 8;
            uint32_t off = (uint32_t)(rA * KPAD + cA) * 2;
            ahi[t][ks] = ldm_x4(smb + OFF_XHI + off);
            alo[t][ks] = ldm_x4(smb + OFF_XLO + off);
        }
    }

    float v1[4], v2[4];
    int   vi[4];
#pragma unroll
    for (int s = 0; s < 4; s++) { v1[s] = -FLT_MAX; v2[s] = -FLT_MAX; vi[s] = 0; }

    // ---- 3. code chunks of 128 ----
    for (int chunk = 0; chunk < 8; chunk++) {
        __syncthreads();                       // previous chunk's ldmatrix done
        // cooperative load of e chunk (hi/lo), 16B per thread-iter
        {
            const uint4* sh = (const uint4*)(g_ehi + (size_t)chunk * 128 * DIMD);
            const uint4* sl = (const uint4*)(g_elo + (size_t)chunk * 128 * DIMD);
#pragma unroll
            for (int i = 0; i < 8; i++) {
                int idx  = tid + i * 256;      // 0..2047
                int code = idx >> 4, ko = (idx & 15) * 8;
                uint32_t doff = (uint32_t)(code * KPAD + ko) * 2;
                *(uint4*)(smem + OFF_EHI + doff) = sh[idx];
                *(uint4*)(smem + OFF_ELO + doff) = sl[idx];
            }
        }
        __syncthreads();

        for (int nt = 0; nt < 16; nt++) {
            const int n0 = nt * 8;
            float4 acc0 = {0.f, 0.f, 0.f, 0.f};
            float4 acc1 = {0.f, 0.f, 0.f, 0.f};
            const uint32_t brow = (uint32_t)((n0 + (lane & 7)) * KPAD + (lane >> 3) * 8) * 2;
#pragma unroll
            for (int kg = 0; kg < 4; kg++) {
                uint4 bh = ldm_x4(smb + OFF_EHI + brow + kg * 64);
                uint4 bl = ldm_x4(smb + OFF_ELO + brow + kg * 64);
                mma16816(acc0, ahi[0][2 * kg],     bh.x, bh.y);
                mma16816(acc0, ahi[0][2 * kg + 1], bh.z, bh.w);
                mma16816(acc1, ahi[1][2 * kg],     bh.x, bh.y);
                mma16816(acc1, ahi[1][2 * kg + 1], bh.z, bh.w);
                mma16816(acc0, ahi[0][2 * kg],     bl.x, bl.y);
                mma16816(acc0, ahi[0][2 * kg + 1], bl.z, bl.w);
                mma16816(acc1, ahi[1][2 * kg],     bl.x, bl.y);
                mma16816(acc1, ahi[1][2 * kg + 1], bl.z, bl.w);
                mma16816(acc0, alo[0][2 * kg],     bh.x, bh.y);
                mma16816(acc0, alo[0][2 * kg + 1], bh.z, bh.w);
                mma16816(acc1, alo[1][2 * kg],     bh.x, bh.y);
                mma16816(acc1, alo[1][2 * kg + 1], bh.z, bh.w);
            }
            // epilogue: score = acc - halfnorm, top-2 update (ascending index)
            const int cg = chunk * 128 + n0 + (lane & 3) * 2;
            const float h0 = hn[cg], h1 = hn[cg + 1];
#pragma unroll
            for (int s = 0; s < 4; s++) {
                float s0, s1;
                if (s == 0)      { s0 = acc0.x - h0; s1 = acc0.y - h1; }
                else if (s == 1) { s0 = acc0.z - h0; s1 = acc0.w - h1; }
                else if (s == 2) { s0 = acc1.x - h0; s1 = acc1.y - h1; }
                else             { s0 = acc1.z - h0; s1 = acc1.w - h1; }
                if (s0 > v1[s]) { v2[s] = v1[s]; v1[s] = s0; vi[s] = cg; }
                else if (s0 > v2[s]) v2[s] = s0;
                if (s1 > v1[s]) { v2[s] = v1[s]; v1[s] = s1; vi[s] = cg + 1; }
                else if (s1 > v2[s]) v2[s] = s1;
            }
        }
    }

    // ---- 4. quad merge (lanes sharing a row differ in lane&3) ----
#pragma unroll
    for (int s = 0; s < 4; s++) {
#pragma unroll
        for (int d = 1; d <= 2; d <<= 1) {
            float o1 = __shfl_xor_sync(0xFFFFFFFF, v1[s], d);
            float o2 = __shfl_xor_sync(0xFFFFFFFF, v2[s], d);
            int   oi = __shfl_xor_sync(0xFFFFFFFF, vi[s], d);
            if (o1 > v1[s]) { v2[s] = fmaxf(v1[s], o2); v1[s] = o1; vi[s] = oi; }
            else if (o1 == v1[s]) { v2[s] = v1[s]; if (oi < vi[s]) vi[s] = oi; }
            else v2[s] = fmaxf(v2[s], o1);
        }
        if ((lane & 3) == 0) {
            int row = w * 32 + (s >> 1) * 16 + (s & 1) * 8 + (lane >> 2);
            rv1[row] = v1[s];
            rv2[row] = v2[s];
            rvi[row] = vi[s];
        }
    }
    __syncthreads();

    // ---- 5. per-row results: flag / used / index / loss term ----
    {
        const int r = tid;
        const int n = b_ * TT + t0 + r;
        float xxv = xx_sm[r];
        float w1 = rv1[r], w2 = rv2[r];
        int   widx = rvi[r];
        int E = (int)((__float_as_uint(xxv) >> 23) & 0xFF) - 127;
        float stau = __uint_as_float((unsigned)(E - 21 + 127) << 23);
        if (w1 - w2 < stau) {
            int slot = atomicAdd(&g_flagcount, 1);
            if (slot < FLAGCAP) g_flagged[slot] = n;
        } else {
            g_used[widx] = 1u;
        }
        out[QELEMS + n] = (float)widx;
        sidx[r] = widx;
        red[r]  = fmaf(-2.0f, w1, xxv);      // ||x - e||^2 for this row
    }
    __syncthreads();
    // loss partial reduce (256 values)
    if (tid < 128) red[tid] += red[tid + 128];
    __syncthreads();
    if (tid < 64) red[tid] += red[tid + 64];
    __syncthreads();
    if (tid < 32) {
        float s = red[tid] + red[tid + 32];
#pragma unroll
        for (int o = 16; o > 0; o >>= 1) s += __shfl_down_sync(0xFFFFFFFF, s, o);
        if (tid == 0) g_partial[blockIdx.x] = s;
    }

    // ---- 6. gather: stage selected codebook rows (alias smem), write [B,D,T] ----
    float* qs = (float*)(smem + OFF_QS);     // [256][stride 129]
    {
        const float4* er = (const float4*)(embed + (size_t)sidx[tid] * DIMD);
        float* qrow = qs + tid * 129;
#pragma unroll 8
        for (int q = 0; q < 32; q++) {
            float4 v = er[q];
            qrow[q * 4 + 0] = v.x; qrow[q * 4 + 1] = v.y;
            qrow[q * 4 + 2] = v.z; qrow[q * 4 + 3] = v.w;
        }
    }
    __syncthreads();
    {
        float* ob = out + (size_t)b_ * DIMD * TT + t0 + tid;
        const float* qrow = qs + tid * 129;
#pragma unroll 8
        for (int d = 0; d < 128; d++)
            ob[(size_t)d * TT] = qrow[d];     // coalesced in tid
    }
}

// ---------------------------------------------------------------------------
// Kernel 2: exact reference-arithmetic replication for flagged rows; rewrites
// index, quantized row, and used-mark for those rows.
// ---------------------------------------------------------------------------
__global__ __launch_bounds__(256, 1)
void repair_kernel(const float* __restrict__ x, const float* __restrict__ embed,
                   float* __restrict__ out) {
    __shared__ float xv[128];
    __shared__ float xxs;
    __shared__ float rv[256];
    __shared__ int   rix[256];
    const int tid = threadIdx.x;
    int nflag = *(volatile int*)&g_flagcount;
    if (nflag > FLAGCAP) nflag = FLAGCAP;

    for (int f = blockIdx.x; f < nflag; f += gridDim.x) {
        int n = g_flagged[f];
        int b = n >> 12, t = n & 4095;
        if (tid < 128) xv[tid] = x[(size_t)b * DIMD * TT + (size_t)tid * TT + t];
        __syncthreads();
        if (tid == 0) {
            float s = 0.f;
            for (int k = 0; k < 128; k++)
                s = __fadd_rn(s, __fmul_rn(xv[k], xv[k]));
            xxs = s;
        }
        __syncthreads();
        float xx = xxs;

        float bd = 3.4e38f;
        int   bj = 0;
#pragma unroll 1
        for (int q = 0; q < 4; q++) {
            int j = tid * 4 + q;
            const float* e = embed + (size_t)j * DIMD;
            float xe = 0.f;
            for (int k = 0; k < 128; k++)
                xe = __fadd_rn(xe, __fmul_rn(xv[k], e[k]));
            float s1 = __fadd_rn(xx, __fmul_rn(-2.0f, xe));
            float d2 = __fadd_rn(s1, g_ee[j]);
            if (d2 < bd) { bd = d2; bj = j; }
        }
        rv[tid] = bd; rix[tid] = bj;
        __syncthreads();
        for (int s = 128; s > 0; s >>= 1) {
            if (tid < s) {
                float ov = rv[tid + s]; int oj = rix[tid + s];
                if (ov < rv[tid] || (ov == rv[tid] && oj < rix[tid])) {
                    rv[tid] = ov; rix[tid] = oj;
                }
            }
            __syncthreads();
        }
        int idx = rix[0];
        if (tid == 0) {
            g_used[idx] = 1u;
            out[QELEMS + n] = (float)idx;
        }
        if (tid < 128)
            out[(size_t)b * DIMD * TT + (size_t)tid * TT + t] =
                embed[(size_t)idx * DIMD + tid];
        __syncthreads();
    }
}

// ---------------------------------------------------------------------------
// Kernel 3: deterministic final reduction -> loss, utilization
// ---------------------------------------------------------------------------
__global__ void finalize_kernel(float* __restrict__ out) {
    __shared__ float rs[512];
    __shared__ float us[512];
    int tid = threadIdx.x;
    rs[tid] = (tid < NBLK) ? g_partial[tid] : 0.f;
    us[tid] = (float)(g_used[tid] + g_used[tid + 512]);
    __syncthreads();
    for (int s = 256; s > 0; s >>= 1) {
        if (tid < s) { rs[tid] += rs[tid + s]; us[tid] += us[tid + s]; }
        __syncthreads();
    }
    if (tid == 0) {
        out[QELEMS + NTOT]     = 2.0f * rs[0] / (float)QELEMS;  // 2*mean(diff^2)
        out[QELEMS + NTOT + 1] = us[0] / (float)NC;
    }
}

// ---------------------------------------------------------------------------
extern "C" void kernel_launch(void* const* d_in, const int* in_sizes, int n_in,
                              void* d_out, int out_size) {
    (void)in_sizes; (void)n_in; (void)out_size;
    const float* x     = (const float*)d_in[0];
    const float* embed = (const float*)d_in[1];
    float*       out   = (float*)d_out;

    cudaFuncSetAttribute(vq_main_kernel,
                         cudaFuncAttributeMaxDynamicSharedMemorySize, SMEM_MAIN);

    prep_kernel<<<4, 256>>>(embed);
    vq_main_kernel<<<NBLK, 256, SMEM_MAIN>>>(x, embed, out);
    repair_kernel<<<148, 256>>>(x, embed, out);
    finalize_kernel<<<1, 512>>>(out);
}